// round 11
// baseline (speedup 1.0000x reference)
#include <cuda_runtime.h>
#include <cuda_fp16.h>
#include <cstdint>

#define BATCH 32
#define NN    2048
#define CC    8
#define FF    128
#define OO    128
#define MT    64               // nodes per tile
#define NTILES 1024            // (BATCH*NN)/MT
#define GRID   148
#define NTHREADS 512           // 8 consumer + 8 producer warps

// ---- smem layout (bytes) ----
// A(buf,term): 2 bufs x 3 terms x 16KB = 96KB ; B(term): 3 x 32KB = 96KB
#define SM_A(buf, term) ((buf) * 49152 + (term) * 16384)
#define SM_B(term)      (98304 + (term) * 32768)
#define SM_TOTAL        196608

// fp16 image of nodes (built in-kernel each launch) + global soft-barrier counter
__device__ __align__(16) __half g_nodes16[BATCH * NN * FF];   // 16 MB
__device__ unsigned long long g_ctr = 0;                       // monotonic across replays

// swizzled byte offset of (row, k) in a [row][k] fp16 tile with 256B rows
__device__ __forceinline__ uint32_t tile_off(int row, int k) {
    return (uint32_t)(row * 256 + ((((k >> 3) & 15) ^ (row & 7)) << 4) + (k & 7) * 2);
}

__device__ __forceinline__ uint32_t smem_u32(const void* p) {
    uint32_t a;
    asm("{ .reg .u64 t; cvta.to.shared.u64 t, %1; cvt.u32.u64 %0, t; }" : "=r"(a) : "l"(p));
    return a;
}
__device__ __forceinline__ void ldsm4(uint32_t* r, uint32_t addr) {
    asm volatile("ldmatrix.sync.aligned.m8n8.x4.shared.b16 {%0,%1,%2,%3}, [%4];"
        : "=r"(r[0]), "=r"(r[1]), "=r"(r[2]), "=r"(r[3]) : "r"(addr));
}
__device__ __forceinline__ void mma16816(float* d, const uint32_t* a, const uint32_t* b) {
    asm volatile("mma.sync.aligned.m16n8k16.row.col.f32.f16.f16.f32 "
        "{%0,%1,%2,%3}, {%4,%5,%6,%7}, {%8,%9}, {%0,%1,%2,%3};"
        : "+f"(d[0]), "+f"(d[1]), "+f"(d[2]), "+f"(d[3])
        : "r"(a[0]), "r"(a[1]), "r"(a[2]), "r"(a[3]), "r"(b[0]), "r"(b[1]));
}
__device__ __forceinline__ uint32_t packh2(float a, float b) {
    __half2 h = __halves2half2(__float2half_rn(a), __float2half_rn(b));
    return *reinterpret_cast<uint32_t*>(&h);
}
__device__ __forceinline__ void store_h4(char* smem, int base, int m, int k4, float4 v) {
    uint2 u;
    u.x = packh2(v.x, v.y);
    u.y = packh2(v.z, v.w);
    *reinterpret_cast<uint2*>(smem + base + tile_off(m, k4 * 4)) = u;
}

#define BAR_SYNC(id)   asm volatile("bar.sync %0, %1;"   :: "r"(id), "r"(NTHREADS) : "memory")
#define BAR_ARRIVE(id) asm volatile("bar.arrive %0, %1;" :: "r"(id), "r"(NTHREADS) : "memory")
#define MEMBAR_CTA()   asm volatile("membar.cta;" ::: "memory")

// build the three 64x128 A tiles (x, agg_r, agg_l) from the fp16 node image
__device__ __forceinline__ void build_tile(char* smem, int buf, int tile,
                                           const int* __restrict__ children,
                                           int pw, int lane)
{
    const int gn0 = tile * MT;
    const int b   = gn0 >> 11;                 // / NN
    const int n0  = gn0 - b * NN;
    const __half* __restrict__ nodesB = g_nodes16 + (size_t)b * NN * FF;
    const int4* __restrict__ chp4 = reinterpret_cast<const int4*>(
        children + (size_t)gn0 * CC) + (size_t)pw * 16;   // 2 int4 per node

    int4 ci0 = chp4[0];
    int4 ci1 = chp4[1];

#pragma unroll
    for (int p = 0; p < 8; ++p) {
        const int m = pw * 8 + p;              // 0..63

        int ch[CC] = {ci0.x, ci0.y, ci0.z, ci0.w, ci1.x, ci1.y, ci1.z, ci1.w};
        if (p < 7) {
            ci0 = chp4[(p + 1) * 2];
            ci1 = chp4[(p + 1) * 2 + 1];
        }

        // x row: straight swizzled copy (already fp16)
        const uint2 xv = *reinterpret_cast<const uint2*>(
            nodesB + (size_t)(n0 + m) * FF + lane * 4);
        *reinterpret_cast<uint2*>(smem + SM_A(buf, 0) + tile_off(m, lane * 4)) = xv;

        int ns = 0;
#pragma unroll
        for (int c = 0; c < CC; ++c) ns += (ch[c] != 0);
        const float rdenom = (ns > 1) ? __frcp_rn((float)ns - 1.0f) : 0.0f;
        float crv[CC], clv[CC];
#pragma unroll
        for (int c = 0; c < CC; ++c) {
            const float mfl = (ch[c] != 0) ? 1.0f : 0.0f;
            float cr;
            if (ns == 1) cr = (c == 0) ? 0.5f : 0.0f;
            else         cr = (float)c * mfl * rdenom;
            crv[c] = cr * mfl;
            clv[c] = (1.0f - cr) * mfl;
        }

        float4 r; r.x = r.y = r.z = r.w = 0.f;
        float4 l; l.x = l.y = l.z = l.w = 0.f;
        const __half* base = nodesB + lane * 4;
#pragma unroll
        for (int c = 0; c < CC; ++c) {
            const uint2 raw = *reinterpret_cast<const uint2*>(base + (size_t)ch[c] * FF);
            const float2 f0 = __half22float2(*reinterpret_cast<const __half2*>(&raw.x));
            const float2 f1 = __half22float2(*reinterpret_cast<const __half2*>(&raw.y));
            r.x += crv[c] * f0.x; r.y += crv[c] * f0.y; r.z += crv[c] * f1.x; r.w += crv[c] * f1.y;
            l.x += clv[c] * f0.x; l.y += clv[c] * f0.y; l.z += clv[c] * f1.x; l.w += clv[c] * f1.y;
        }
        store_h4(smem, SM_A(buf, 1), m, lane, r);
        store_h4(smem, SM_A(buf, 2), m, lane, l);
    }
}

__global__ void __launch_bounds__(NTHREADS, 1)
btconv_ws_kernel(const float* __restrict__ nodes,
                 const int*   __restrict__ children,
                 const float* __restrict__ w_t,
                 const float* __restrict__ w_l,
                 const float* __restrict__ w_r,
                 const float* __restrict__ bias,
                 float*       __restrict__ out)
{
    extern __shared__ char smem[];
    const uint32_t sb = smem_u32(smem);
    const int tid  = threadIdx.x;
    const int wid  = tid >> 5;       // 0..15
    const int lane = tid & 31;

    // ---------- B build: W -> swizzled fp16 images [n][k] ----------
    for (int u = tid; u < 3 * 16 * 128; u += NTHREADS) {
        const int n    = u & 127;
        const int kg   = (u >> 7) & 15;
        const int term = u >> 11;
        const float* src = (term == 0) ? w_t : (term == 1) ? w_r : w_l;
        float f[8];
#pragma unroll
        for (int j = 0; j < 8; ++j)
            f[j] = __ldg(src + (size_t)(kg * 8 + j) * OO + n);
        uint4 v;
        v.x = packh2(f[0], f[1]); v.y = packh2(f[2], f[3]);
        v.z = packh2(f[4], f[5]); v.w = packh2(f[6], f[7]);
        *reinterpret_cast<uint4*>(smem + SM_B(term) + tile_off(n, kg * 8)) = v;
    }

    // ---------- nodes -> fp16 image (grid-cooperative) ----------
    {
        const float4* __restrict__ src4 = reinterpret_cast<const float4*>(nodes);
        uint4* __restrict__ dst4 = reinterpret_cast<uint4*>(g_nodes16);
        const int total = BATCH * NN * FF / 8;          // 1,048,576 chunks of 8
        const int stride = GRID * NTHREADS;
        for (int i = blockIdx.x * NTHREADS + tid; i < total; i += stride) {
            const float4 f0 = src4[i * 2];
            const float4 f1 = src4[i * 2 + 1];
            uint4 o;
            o.x = packh2(f0.x, f0.y); o.y = packh2(f0.z, f0.w);
            o.z = packh2(f1.x, f1.y); o.w = packh2(f1.z, f1.w);
            dst4[i] = o;
        }
    }
    // soft global barrier (all 148 blocks co-resident; monotonic counter)
    __threadfence();
    __syncthreads();
    if (tid == 0) {
        const unsigned long long old = atomicAdd(&g_ctr, 1ULL);
        const unsigned long long target = (old / GRID) * GRID + GRID;
        volatile unsigned long long* p = &g_ctr;
        while (*p < target) {}
    }
    __threadfence();
    __syncthreads();

    if (wid >= 8) {
        // ================= PRODUCER (warps 8..15) =================
        const int pw = wid - 8;
        int i = 0;
        for (int tile = blockIdx.x; tile < NTILES; tile += GRID, ++i) {
            const int buf = i & 1;
            if (i >= 2) BAR_SYNC(3 + buf);          // wait: consumers freed this buf
            build_tile(smem, buf, tile, children, pw, lane);
            MEMBAR_CTA();
            BAR_ARRIVE(1 + buf);                    // signal: buf ready
        }
    } else {
        // ================= CONSUMER (warps 0..7), 32m x 32n =================
        const int warp_m = (wid & 1) * 32;
        const int warp_n = (wid >> 1) * 32;

        uint32_t a_base[2], a_sx[2], b_base[2], b_sx[2];
#pragma unroll
        for (int mt = 0; mt < 2; ++mt) {
            const int m = warp_m + mt * 16 + (lane & 15);
            a_base[mt] = (uint32_t)(m * 256);
            a_sx[mt]   = (uint32_t)(m & 7);
        }
#pragma unroll
        for (int np = 0; np < 2; ++np) {
            const int n = warp_n + np * 16 + (lane & 7) + ((lane >> 4) << 3);
            b_base[np] = (uint32_t)(n * 256);
            b_sx[np]   = (uint32_t)(n & 7);
        }
        const uint32_t a_cadd = (uint32_t)(lane >> 4);
        const uint32_t b_cadd = (uint32_t)((lane >> 3) & 1);

        float bv[8];
#pragma unroll
        for (int nt = 0; nt < 4; ++nt) {
            const int n = warp_n + nt * 8 + (lane & 3) * 2;
            bv[nt * 2 + 0] = __ldg(bias + n);
            bv[nt * 2 + 1] = __ldg(bias + n + 1);
        }

        int i = 0;
        for (int tile = blockIdx.x; tile < NTILES; tile += GRID, ++i) {
            const int buf = i & 1;
            BAR_SYNC(1 + buf);                      // wait: buf ready

            float acc[2][4][4];
#pragma unroll
            for (int a = 0; a < 2; ++a)
#pragma unroll
                for (int j = 0; j < 4; ++j)
#pragma unroll
                    for (int q = 0; q < 4; ++q) acc[a][j][q] = 0.f;

#pragma unroll
            for (int term = 0; term < 3; ++term) {
                const int a_off = SM_A(buf, term);
                const int b_off = SM_B(term);
#pragma unroll
                for (int ks = 0; ks < 8; ++ks) {
                    uint32_t af[2][4], bf[2][4];
#pragma unroll
                    for (int mt = 0; mt < 2; ++mt) {
                        const uint32_t ac = a_base[mt] + ((((uint32_t)(ks * 2) + a_cadd) ^ a_sx[mt]) << 4);
                        ldsm4(af[mt], sb + a_off + ac);
                    }
#pragma unroll
                    for (int np = 0; np < 2; ++np) {
                        const uint32_t bc = b_base[np] + ((((uint32_t)(ks * 2) + b_cadd) ^ b_sx[np]) << 4);
                        ldsm4(bf[np], sb + b_off + bc);
                    }
#pragma unroll
                    for (int mt = 0; mt < 2; ++mt)
#pragma unroll
                        for (int np = 0; np < 2; ++np)
#pragma unroll
                            for (int ns = 0; ns < 2; ++ns)
                                mma16816(acc[mt][np * 2 + ns], af[mt], bf[np] + ns * 2);
                }
            }

            // release the buffer (all smem reads done)
            if (tile + 2 * GRID < NTILES) BAR_ARRIVE(3 + buf);

            // epilogue: bias + relu + store
            const int gn0 = tile * MT;
#pragma unroll
            for (int mt = 0; mt < 2; ++mt) {
#pragma unroll
                for (int ii = 0; ii < 2; ++ii) {
                    const int m = gn0 + warp_m + mt * 16 + (lane >> 2) + ii * 8;
                    float* orow = out + (size_t)m * OO;
#pragma unroll
                    for (int nt = 0; nt < 4; ++nt) {
                        const int n = warp_n + nt * 8 + (lane & 3) * 2;
                        float2 o;
                        o.x = fmaxf(acc[mt][nt][ii * 2 + 0] + bv[nt * 2 + 0], 0.f);
                        o.y = fmaxf(acc[mt][nt][ii * 2 + 1] + bv[nt * 2 + 1], 0.f);
                        *reinterpret_cast<float2*>(orow + n) = o;
                    }
                }
            }
        }
    }
}

extern "C" void kernel_launch(void* const* d_in, const int* in_sizes, int n_in,
                              void* d_out, int out_size) {
    const float* nodes    = (const float*)d_in[0];   // [B,N,F]
    const int*   children = (const int*)  d_in[1];   // [B,N,C]
    const float* w_t      = (const float*)d_in[2];   // [F,O]
    const float* w_l      = (const float*)d_in[3];   // [F,O]
    const float* w_r      = (const float*)d_in[4];   // [F,O]
    const float* bias     = (const float*)d_in[5];   // [O]
    float* out = (float*)d_out;                      // [B,N,O]

    cudaFuncSetAttribute(btconv_ws_kernel, cudaFuncAttributeMaxDynamicSharedMemorySize, SM_TOTAL);
    btconv_ws_kernel<<<GRID, NTHREADS, SM_TOTAL>>>(nodes, children, w_t, w_l, w_r, bias, out);
}

// round 12
// speedup vs baseline: 1.3136x; 1.3136x over previous
#include <cuda_runtime.h>
#include <cuda_fp16.h>
#include <cstdint>

#define BATCH 32
#define NN    2048
#define CC    8
#define FF    128
#define OO    128
#define MT    64               // nodes per tile
#define NTILES 1024            // (BATCH*NN)/MT
#define GRID   148
#define NTHREADS 768           // 8 consumer warps + 16 producer warps

// ---- smem layout (bytes) ----
// A(buf,term): 2 bufs x 3 terms x 16KB = 96KB ; B(term): 3 x 32KB = 96KB
#define SM_A(buf, term) ((buf) * 49152 + (term) * 16384)
#define SM_B(term)      (98304 + (term) * 32768)
#define SM_TOTAL        196608

// swizzled byte offset of (row, k) in a [row][k] fp16 tile with 256B rows
__device__ __forceinline__ uint32_t tile_off(int row, int k) {
    return (uint32_t)(row * 256 + ((((k >> 3) & 15) ^ (row & 7)) << 4) + (k & 7) * 2);
}

__device__ __forceinline__ uint32_t smem_u32(const void* p) {
    uint32_t a;
    asm("{ .reg .u64 t; cvta.to.shared.u64 t, %1; cvt.u32.u64 %0, t; }" : "=r"(a) : "l"(p));
    return a;
}
__device__ __forceinline__ void ldsm4(uint32_t* r, uint32_t addr) {
    asm volatile("ldmatrix.sync.aligned.m8n8.x4.shared.b16 {%0,%1,%2,%3}, [%4];"
        : "=r"(r[0]), "=r"(r[1]), "=r"(r[2]), "=r"(r[3]) : "r"(addr));
}
__device__ __forceinline__ void mma16816(float* d, const uint32_t* a, const uint32_t* b) {
    asm volatile("mma.sync.aligned.m16n8k16.row.col.f32.f16.f16.f32 "
        "{%0,%1,%2,%3}, {%4,%5,%6,%7}, {%8,%9}, {%0,%1,%2,%3};"
        : "+f"(d[0]), "+f"(d[1]), "+f"(d[2]), "+f"(d[3])
        : "r"(a[0]), "r"(a[1]), "r"(a[2]), "r"(a[3]), "r"(b[0]), "r"(b[1]));
}
__device__ __forceinline__ uint32_t packh2(float a, float b) {
    __half2 h = __halves2half2(__float2half_rn(a), __float2half_rn(b));
    return *reinterpret_cast<uint32_t*>(&h);
}
__device__ __forceinline__ void store_h4(char* smem, int base, int m, int k4, float4 v) {
    uint2 u;
    u.x = packh2(v.x, v.y);
    u.y = packh2(v.z, v.w);
    *reinterpret_cast<uint2*>(smem + base + tile_off(m, k4 * 4)) = u;
}

#define BAR_SYNC(id)   asm volatile("bar.sync %0, %1;"   :: "r"(id), "r"(NTHREADS) : "memory")
#define BAR_ARRIVE(id) asm volatile("bar.arrive %0, %1;" :: "r"(id), "r"(NTHREADS) : "memory")
#define MEMBAR_CTA()   asm volatile("membar.cta;" ::: "memory")

// build 4 nodes of the three 64x128 A tiles — producer warps (pw = 0..15)
__device__ __forceinline__ void build_tile(char* smem, int buf, int tile,
                                           const float* __restrict__ nodes,
                                           const int*   __restrict__ children,
                                           int pw, int lane)
{
    const int gn0 = tile * MT;
    const int b   = gn0 >> 11;                 // / NN
    const int n0  = gn0 - b * NN;
    const float* __restrict__ nodesB = nodes + (size_t)b * NN * FF;
    const int4* __restrict__ chp4 = reinterpret_cast<const int4*>(
        children + (size_t)gn0 * CC) + (size_t)pw * 8;    // 4 nodes x 2 int4

    int4 ci0 = chp4[0];
    int4 ci1 = chp4[1];

#pragma unroll
    for (int p = 0; p < 4; ++p) {
        const int m = pw * 4 + p;              // 0..63

        int ch[CC] = {ci0.x, ci0.y, ci0.z, ci0.w, ci1.x, ci1.y, ci1.z, ci1.w};
        if (p < 3) {
            ci0 = chp4[(p + 1) * 2];
            ci1 = chp4[(p + 1) * 2 + 1];
        }

        const float4 xv = *reinterpret_cast<const float4*>(
            nodesB + (size_t)(n0 + m) * FF + lane * 4);

        int ns = 0;
#pragma unroll
        for (int c = 0; c < CC; ++c) ns += (ch[c] != 0);
        const float rdenom = (ns > 1) ? __frcp_rn((float)ns - 1.0f) : 0.0f;
        float crv[CC], clv[CC];
#pragma unroll
        for (int c = 0; c < CC; ++c) {
            const float mfl = (ch[c] != 0) ? 1.0f : 0.0f;
            float cr;
            if (ns == 1) cr = (c == 0) ? 0.5f : 0.0f;
            else         cr = (float)c * mfl * rdenom;
            crv[c] = cr * mfl;
            clv[c] = (1.0f - cr) * mfl;
        }

        float4 r; r.x = r.y = r.z = r.w = 0.f;
        float4 l; l.x = l.y = l.z = l.w = 0.f;
        const float* base = nodesB + lane * 4;
#pragma unroll
        for (int c = 0; c < CC; ++c) {
            const float4 v = *reinterpret_cast<const float4*>(base + (size_t)ch[c] * FF);
            r.x += crv[c] * v.x; r.y += crv[c] * v.y; r.z += crv[c] * v.z; r.w += crv[c] * v.w;
            l.x += clv[c] * v.x; l.y += clv[c] * v.y; l.z += clv[c] * v.z; l.w += clv[c] * v.w;
        }
        store_h4(smem, SM_A(buf, 0), m, lane, xv);
        store_h4(smem, SM_A(buf, 1), m, lane, r);
        store_h4(smem, SM_A(buf, 2), m, lane, l);
    }
}

__global__ void __launch_bounds__(NTHREADS, 1)
btconv_ws_kernel(const float* __restrict__ nodes,
                 const int*   __restrict__ children,
                 const float* __restrict__ w_t,
                 const float* __restrict__ w_l,
                 const float* __restrict__ w_r,
                 const float* __restrict__ bias,
                 float*       __restrict__ out)
{
    extern __shared__ char smem[];
    const uint32_t sb = smem_u32(smem);
    const int tid  = threadIdx.x;
    const int wid  = tid >> 5;       // 0..23
    const int lane = tid & 31;

    // ---------- B build (all 768 threads): W -> swizzled fp16 images [n][k] ----------
    for (int u = tid; u < 3 * 16 * 128; u += NTHREADS) {
        const int n    = u & 127;
        const int kg   = (u >> 7) & 15;
        const int term = u >> 11;
        const float* src = (term == 0) ? w_t : (term == 1) ? w_r : w_l;
        float f[8];
#pragma unroll
        for (int j = 0; j < 8; ++j)
            f[j] = __ldg(src + (size_t)(kg * 8 + j) * OO + n);
        uint4 v;
        v.x = packh2(f[0], f[1]); v.y = packh2(f[2], f[3]);
        v.z = packh2(f[4], f[5]); v.w = packh2(f[6], f[7]);
        *reinterpret_cast<uint4*>(smem + SM_B(term) + tile_off(n, kg * 8)) = v;
    }
    __syncthreads();

    if (wid >= 8) {
        // ================= PRODUCER (warps 8..23, 4 nodes each) =================
        const int pw = wid - 8;
        int i = 0;
        for (int tile = blockIdx.x; tile < NTILES; tile += GRID, ++i) {
            const int buf = i & 1;
            if (i >= 2) BAR_SYNC(3 + buf);          // wait: consumers freed this buf
            build_tile(smem, buf, tile, nodes, children, pw, lane);
            MEMBAR_CTA();
            BAR_ARRIVE(1 + buf);                    // signal: buf ready
        }
    } else {
        // ================= CONSUMER (warps 0..7), 32m x 32n =================
        const int warp_m = (wid & 1) * 32;
        const int warp_n = (wid >> 1) * 32;

        uint32_t a_base[2], a_sx[2], b_base[2], b_sx[2];
#pragma unroll
        for (int mt = 0; mt < 2; ++mt) {
            const int m = warp_m + mt * 16 + (lane & 15);
            a_base[mt] = (uint32_t)(m * 256);
            a_sx[mt]   = (uint32_t)(m & 7);
        }
#pragma unroll
        for (int np = 0; np < 2; ++np) {
            const int n = warp_n + np * 16 + (lane & 7) + ((lane >> 4) << 3);
            b_base[np] = (uint32_t)(n * 256);
            b_sx[np]   = (uint32_t)(n & 7);
        }
        const uint32_t a_cadd = (uint32_t)(lane >> 4);
        const uint32_t b_cadd = (uint32_t)((lane >> 3) & 1);

        float bv[8];
#pragma unroll
        for (int nt = 0; nt < 4; ++nt) {
            const int n = warp_n + nt * 8 + (lane & 3) * 2;
            bv[nt * 2 + 0] = __ldg(bias + n);
            bv[nt * 2 + 1] = __ldg(bias + n + 1);
        }

        int i = 0;
        for (int tile = blockIdx.x; tile < NTILES; tile += GRID, ++i) {
            const int buf = i & 1;
            BAR_SYNC(1 + buf);                      // wait: buf ready

            float acc[2][4][4];
#pragma unroll
            for (int a = 0; a < 2; ++a)
#pragma unroll
                for (int j = 0; j < 4; ++j)
#pragma unroll
                    for (int q = 0; q < 4; ++q) acc[a][j][q] = 0.f;

#pragma unroll
            for (int term = 0; term < 3; ++term) {
                const int a_off = SM_A(buf, term);
                const int b_off = SM_B(term);
#pragma unroll
                for (int ks = 0; ks < 8; ++ks) {
                    uint32_t af[2][4], bf[2][4];
#pragma unroll
                    for (int mt = 0; mt < 2; ++mt) {
                        const uint32_t ac = a_base[mt] + ((((uint32_t)(ks * 2) + a_cadd) ^ a_sx[mt]) << 4);
                        ldsm4(af[mt], sb + a_off + ac);
                    }
#pragma unroll
                    for (int np = 0; np < 2; ++np) {
                        const uint32_t bc = b_base[np] + ((((uint32_t)(ks * 2) + b_cadd) ^ b_sx[np]) << 4);
                        ldsm4(bf[np], sb + b_off + bc);
                    }
#pragma unroll
                    for (int mt = 0; mt < 2; ++mt)
#pragma unroll
                        for (int np = 0; np < 2; ++np)
#pragma unroll
                            for (int ns = 0; ns < 2; ++ns)
                                mma16816(acc[mt][np * 2 + ns], af[mt], bf[np] + ns * 2);
                }
            }

            // release the buffer (all smem reads done)
            if (tile + 2 * GRID < NTILES) BAR_ARRIVE(3 + buf);

            // epilogue: bias + relu + store
            const int gn0 = tile * MT;
#pragma unroll
            for (int mt = 0; mt < 2; ++mt) {
#pragma unroll
                for (int ii = 0; ii < 2; ++ii) {
                    const int m = gn0 + warp_m + mt * 16 + (lane >> 2) + ii * 8;
                    float* orow = out + (size_t)m * OO;
#pragma unroll
                    for (int nt = 0; nt < 4; ++nt) {
                        const int n = warp_n + nt * 8 + (lane & 3) * 2;
                        float2 o;
                        o.x = fmaxf(acc[mt][nt][ii * 2 + 0] + bv[nt * 2 + 0], 0.f);
                        o.y = fmaxf(acc[mt][nt][ii * 2 + 1] + bv[nt * 2 + 1], 0.f);
                        *reinterpret_cast<float2*>(orow + n) = o;
                    }
                }
            }
        }
    }
}

extern "C" void kernel_launch(void* const* d_in, const int* in_sizes, int n_in,
                              void* d_out, int out_size) {
    const float* nodes    = (const float*)d_in[0];   // [B,N,F]
    const int*   children = (const int*)  d_in[1];   // [B,N,C]
    const float* w_t      = (const float*)d_in[2];   // [F,O]
    const float* w_l      = (const float*)d_in[3];   // [F,O]
    const float* w_r      = (const float*)d_in[4];   // [F,O]
    const float* bias     = (const float*)d_in[5];   // [O]
    float* out = (float*)d_out;                      // [B,N,O]

    cudaFuncSetAttribute(btconv_ws_kernel, cudaFuncAttributeMaxDynamicSharedMemorySize, SM_TOTAL);
    btconv_ws_kernel<<<GRID, NTHREADS, SM_TOTAL>>>(nodes, children, w_t, w_l, w_r, bias, out);
}

// round 13
// speedup vs baseline: 1.3712x; 1.0439x over previous
#include <cuda_runtime.h>
#include <cuda_fp16.h>
#include <cstdint>

#define BATCH 32
#define NN    2048
#define CC    8
#define FF    128
#define OO    128
#define MT    64               // nodes per tile
#define NTILES 1024            // (BATCH*NN)/MT
#define GRID   148
#define NTHREADS 768           // 8 consumer warps + 16 producer warps

// ---- smem layout (bytes) ----
// A(buf,term): 2 bufs x 3 terms x 16KB = 96KB ; B(term): 3 x 32KB = 96KB
#define SM_A(buf, term) ((buf) * 49152 + (term) * 16384)
#define SM_B(term)      (98304 + (term) * 32768)
#define SM_TOTAL        196608

// swizzled byte offset of (row, k) in a [row][k] fp16 tile with 256B rows
__device__ __forceinline__ uint32_t tile_off(int row, int k) {
    return (uint32_t)(row * 256 + ((((k >> 3) & 15) ^ (row & 7)) << 4) + (k & 7) * 2);
}

__device__ __forceinline__ uint32_t smem_u32(const void* p) {
    uint32_t a;
    asm("{ .reg .u64 t; cvta.to.shared.u64 t, %1; cvt.u32.u64 %0, t; }" : "=r"(a) : "l"(p));
    return a;
}
__device__ __forceinline__ void ldsm4(uint32_t* r, uint32_t addr) {
    asm volatile("ldmatrix.sync.aligned.m8n8.x4.shared.b16 {%0,%1,%2,%3}, [%4];"
        : "=r"(r[0]), "=r"(r[1]), "=r"(r[2]), "=r"(r[3]) : "r"(addr));
}
__device__ __forceinline__ void mma16816(float* d, const uint32_t* a, const uint32_t* b) {
    asm volatile("mma.sync.aligned.m16n8k16.row.col.f32.f16.f16.f32 "
        "{%0,%1,%2,%3}, {%4,%5,%6,%7}, {%8,%9}, {%0,%1,%2,%3};"
        : "+f"(d[0]), "+f"(d[1]), "+f"(d[2]), "+f"(d[3])
        : "r"(a[0]), "r"(a[1]), "r"(a[2]), "r"(a[3]), "r"(b[0]), "r"(b[1]));
}
__device__ __forceinline__ uint32_t packh2(float a, float b) {
    __half2 h = __halves2half2(__float2half_rn(a), __float2half_rn(b));
    return *reinterpret_cast<uint32_t*>(&h);
}
__device__ __forceinline__ void store_h4(char* smem, int base, int m, int k4, float4 v) {
    uint2 u;
    u.x = packh2(v.x, v.y);
    u.y = packh2(v.z, v.w);
    *reinterpret_cast<uint2*>(smem + base + tile_off(m, k4 * 4)) = u;
}

#define BAR_SYNC(id)   asm volatile("bar.sync %0, %1;"   :: "r"(id), "r"(NTHREADS) : "memory")
#define BAR_ARRIVE(id) asm volatile("bar.arrive %0, %1;" :: "r"(id), "r"(NTHREADS) : "memory")

// build 4 nodes of the three 64x128 A tiles — producer warps (pw = 0..15)
// Uses agg_l = S1 - agg_r  where S1 = sum(mask_c * v_c)  (exact coefficient identity)
__device__ __forceinline__ void build_tile(char* smem, int buf, int tile,
                                           const float* __restrict__ nodes,
                                           const int*   __restrict__ children,
                                           int pw, int lane)
{
    const int gn0 = tile * MT;
    const int b   = gn0 >> 11;                 // / NN
    const int n0  = gn0 - b * NN;
    const float* __restrict__ nodesB = nodes + (size_t)b * NN * FF;
    const int4* __restrict__ chp4 = reinterpret_cast<const int4*>(
        children + (size_t)gn0 * CC) + (size_t)pw * 8;    // 4 nodes x 2 int4

    int4 ci0 = chp4[0];
    int4 ci1 = chp4[1];

#pragma unroll
    for (int p = 0; p < 4; ++p) {
        const int m = pw * 4 + p;              // 0..63

        int ch[CC] = {ci0.x, ci0.y, ci0.z, ci0.w, ci1.x, ci1.y, ci1.z, ci1.w};
        if (p < 3) {
            ci0 = chp4[(p + 1) * 2];
            ci1 = chp4[(p + 1) * 2 + 1];
        }

        const float4 xv = *reinterpret_cast<const float4*>(
            nodesB + (size_t)(n0 + m) * FF + lane * 4);

        int ns = 0;
#pragma unroll
        for (int c = 0; c < CC; ++c) ns += (ch[c] != 0);
        const float rdenom = (ns > 1) ? __frcp_rn((float)ns - 1.0f) : 0.0f;
        float crv[CC], mfl[CC];
#pragma unroll
        for (int c = 0; c < CC; ++c) {
            mfl[c] = (ch[c] != 0) ? 1.0f : 0.0f;
            float cr;
            if (ns == 1) cr = (c == 0) ? 0.5f : 0.0f;
            else         cr = (float)c * rdenom;
            crv[c] = cr * mfl[c];              // masked right coefficient
        }

        float4 r; r.x = r.y = r.z = r.w = 0.f;   // agg_r
        float4 s; s.x = s.y = s.z = s.w = 0.f;   // S1 = masked sum
        const float* base = nodesB + lane * 4;
#pragma unroll
        for (int c = 0; c < CC; ++c) {
            const float4 v = *reinterpret_cast<const float4*>(base + (size_t)ch[c] * FF);
            r.x += crv[c] * v.x; r.y += crv[c] * v.y; r.z += crv[c] * v.z; r.w += crv[c] * v.w;
            s.x += mfl[c] * v.x; s.y += mfl[c] * v.y; s.z += mfl[c] * v.z; s.w += mfl[c] * v.w;
        }
        float4 l;                                // agg_l = S1 - agg_r
        l.x = s.x - r.x; l.y = s.y - r.y; l.z = s.z - r.z; l.w = s.w - r.w;

        store_h4(smem, SM_A(buf, 0), m, lane, xv);
        store_h4(smem, SM_A(buf, 1), m, lane, r);
        store_h4(smem, SM_A(buf, 2), m, lane, l);
    }
}

__global__ void __launch_bounds__(NTHREADS, 1)
btconv_ws_kernel(const float* __restrict__ nodes,
                 const int*   __restrict__ children,
                 const float* __restrict__ w_t,
                 const float* __restrict__ w_l,
                 const float* __restrict__ w_r,
                 const float* __restrict__ bias,
                 float*       __restrict__ out)
{
    extern __shared__ char smem[];
    const uint32_t sb = smem_u32(smem);
    const int tid  = threadIdx.x;
    const int wid  = tid >> 5;       // 0..23
    const int lane = tid & 31;

    // ---------- B build (all 768 threads): W -> swizzled fp16 images [n][k] ----------
    for (int u = tid; u < 3 * 16 * 128; u += NTHREADS) {
        const int n    = u & 127;
        const int kg   = (u >> 7) & 15;
        const int term = u >> 11;
        const float* src = (term == 0) ? w_t : (term == 1) ? w_r : w_l;
        float f[8];
#pragma unroll
        for (int j = 0; j < 8; ++j)
            f[j] = __ldg(src + (size_t)(kg * 8 + j) * OO + n);
        uint4 v;
        v.x = packh2(f[0], f[1]); v.y = packh2(f[2], f[3]);
        v.z = packh2(f[4], f[5]); v.w = packh2(f[6], f[7]);
        *reinterpret_cast<uint4*>(smem + SM_B(term) + tile_off(n, kg * 8)) = v;
    }
    __syncthreads();

    if (wid >= 8) {
        // ================= PRODUCER (warps 8..23, 4 nodes each) =================
        const int pw = wid - 8;
        int i = 0;
        for (int tile = blockIdx.x; tile < NTILES; tile += GRID, ++i) {
            const int buf = i & 1;
            if (i >= 2) BAR_SYNC(3 + buf);          // wait: consumers freed this buf
            build_tile(smem, buf, tile, nodes, children, pw, lane);
            BAR_ARRIVE(1 + buf);                    // signal: buf ready (bar carries cta-scope release)
        }
    } else {
        // ================= CONSUMER (warps 0..7), 32m x 32n =================
        const int warp_m = (wid & 1) * 32;
        const int warp_n = (wid >> 1) * 32;

        uint32_t a_base[2], a_sx[2], b_base[2], b_sx[2];
#pragma unroll
        for (int mt = 0; mt < 2; ++mt) {
            const int m = warp_m + mt * 16 + (lane & 15);
            a_base[mt] = (uint32_t)(m * 256);
            a_sx[mt]   = (uint32_t)(m & 7);
        }
#pragma unroll
        for (int np = 0; np < 2; ++np) {
            const int n = warp_n + np * 16 + (lane & 7) + ((lane >> 4) << 3);
            b_base[np] = (uint32_t)(n * 256);
            b_sx[np]   = (uint32_t)(n & 7);
        }
        const uint32_t a_cadd = (uint32_t)(lane >> 4);
        const uint32_t b_cadd = (uint32_t)((lane >> 3) & 1);

        float bv[8];
#pragma unroll
        for (int nt = 0; nt < 4; ++nt) {
            const int n = warp_n + nt * 8 + (lane & 3) * 2;
            bv[nt * 2 + 0] = __ldg(bias + n);
            bv[nt * 2 + 1] = __ldg(bias + n + 1);
        }

        int i = 0;
        for (int tile = blockIdx.x; tile < NTILES; tile += GRID, ++i) {
            const int buf = i & 1;
            BAR_SYNC(1 + buf);                      // wait: buf ready (bar carries cta-scope acquire)

            float acc[2][4][4];
#pragma unroll
            for (int a = 0; a < 2; ++a)
#pragma unroll
                for (int j = 0; j < 4; ++j)
#pragma unroll
                    for (int q = 0; q < 4; ++q) acc[a][j][q] = 0.f;

#pragma unroll
            for (int term = 0; term < 3; ++term) {
                const int a_off = SM_A(buf, term);
                const int b_off = SM_B(term);
#pragma unroll
                for (int ks = 0; ks < 8; ++ks) {
                    uint32_t af[2][4], bf[2][4];
#pragma unroll
                    for (int mt = 0; mt < 2; ++mt) {
                        const uint32_t ac = a_base[mt] + ((((uint32_t)(ks * 2) + a_cadd) ^ a_sx[mt]) << 4);
                        ldsm4(af[mt], sb + a_off + ac);
                    }
#pragma unroll
                    for (int np = 0; np < 2; ++np) {
                        const uint32_t bc = b_base[np] + ((((uint32_t)(ks * 2) + b_cadd) ^ b_sx[np]) << 4);
                        ldsm4(bf[np], sb + b_off + bc);
                    }
#pragma unroll
                    for (int mt = 0; mt < 2; ++mt)
#pragma unroll
                        for (int np = 0; np < 2; ++np)
#pragma unroll
                            for (int ns = 0; ns < 2; ++ns)
                                mma16816(acc[mt][np * 2 + ns], af[mt], bf[np] + ns * 2);
                }
            }

            // release the buffer (all smem reads done)
            if (tile + 2 * GRID < NTILES) BAR_ARRIVE(3 + buf);

            // epilogue: bias + relu + store
            const int gn0 = tile * MT;
#pragma unroll
            for (int mt = 0; mt < 2; ++mt) {
#pragma unroll
                for (int ii = 0; ii < 2; ++ii) {
                    const int m = gn0 + warp_m + mt * 16 + (lane >> 2) + ii * 8;
                    float* orow = out + (size_t)m * OO;
#pragma unroll
                    for (int nt = 0; nt < 4; ++nt) {
                        const int n = warp_n + nt * 8 + (lane & 3) * 2;
                        float2 o;
                        o.x = fmaxf(acc[mt][nt][ii * 2 + 0] + bv[nt * 2 + 0], 0.f);
                        o.y = fmaxf(acc[mt][nt][ii * 2 + 1] + bv[nt * 2 + 1], 0.f);
                        *reinterpret_cast<float2*>(orow + n) = o;
                    }
                }
            }
        }
    }
}

extern "C" void kernel_launch(void* const* d_in, const int* in_sizes, int n_in,
                              void* d_out, int out_size) {
    const float* nodes    = (const float*)d_in[0];   // [B,N,F]
    const int*   children = (const int*)  d_in[1];   // [B,N,C]
    const float* w_t      = (const float*)d_in[2];   // [F,O]
    const float* w_l      = (const float*)d_in[3];   // [F,O]
    const float* w_r      = (const float*)d_in[4];   // [F,O]
    const float* bias     = (const float*)d_in[5];   // [O]
    float* out = (float*)d_out;                      // [B,N,O]

    cudaFuncSetAttribute(btconv_ws_kernel, cudaFuncAttributeMaxDynamicSharedMemorySize, SM_TOTAL);
    btconv_ws_kernel<<<GRID, NTHREADS, SM_TOTAL>>>(nodes, children, w_t, w_l, w_r, bias, out);
}